// round 6
// baseline (speedup 1.0000x reference)
#include <cuda_runtime.h>

// (B,C,D,H,W) = (4,8,16,256,256), k=3, stride=1, pad=1
#define BC   32
#define DD   16
#define HH   256
#define WW   256
#define HW   (HH*WW)
#define CHV  (DD*HW)

#define TH    16              // tile height
#define TXN   16              // threads in x
#define PXT   4               // pixels per thread (w)
#define TWPIX 64              // tile width in pixels
#define ROWS  (TH+2)          // 18
#define COLS  (TWPIX+2)       // 66
#define TS    (ROWS*COLS)     // 1188
#define NT    (TH*TXN)        // 256

__global__ void __launch_bounds__(NT, 3)
softargmax_kernel(const float* __restrict__ x, float* __restrict__ out)
{
    const int bc = blockIdx.z;
    const int h0 = blockIdx.y * TH;
    const int w0 = blockIdx.x * TWPIX;
    const int tid = threadIdx.x;
    const int tx = tid & (TXN - 1);
    const int ty = tid >> 4;

    // double-buffered (e, e*x) slice tiles
    __shared__ __align__(16) float2 tile[2][TS];

    const float* __restrict__ xc = x + (size_t)bc * CHV;

    // 5 load slots cover TS=1188 (slot4 partial: tid<164)
    int  off[5];
    bool pred[5];
    const bool in4 = (tid + 4 * NT) < TS;
    #pragma unroll
    for (int j = 0; j < 5; j++) {
        int i = tid + j * NT;
        int r = i / COLS, c = i % COLS;
        int hh = h0 + r - 1, ww = w0 + c - 1;
        bool inb = (j < 4) || in4;
        pred[j] = inb && (hh >= 0) && (hh < HH) && (ww >= 0) && (ww < WW);
        off[j]  = pred[j] ? hh * WW + ww : 0;
    }

    float rv[5];
    #pragma unroll
    for (int j = 0; j < 5; j++) rv[j] = pred[j] ? __ldg(xc + off[j]) : 0.f;

    #define PUBLISH(BUF)                                                      \
        _Pragma("unroll")                                                     \
        for (int j = 0; j < 5; j++) {                                         \
            if (j < 4 || in4) {                                               \
                float e = pred[j] ? __expf(rv[j]) : 0.f;                      \
                tile[BUF][tid + j * NT] = make_float2(e, e * rv[j]);          \
            }                                                                 \
        }

    // s[0..3]=sum  s[4..7]=xnum  s[8..11]=ynum  s[12..15]=vnum  (px 0..3)
    #define ACCUM(s, BUF)                                                     \
        _Pragma("unroll")                                                     \
        for (int r = 0; r < 3; r++) {                                         \
            const float2* rowp = &tile[BUF][(ty + r) * COLS + 4 * tx];        \
            const float4 A = *reinterpret_cast<const float4*>(rowp);          \
            const float4 Bq = *reinterpret_cast<const float4*>(rowp + 2);     \
            const float4 Cq = *reinterpret_cast<const float4*>(rowp + 4);     \
            const float e0 = A.x,  v0 = A.y,  e1 = A.z,  v1 = A.w;            \
            const float e2 = Bq.x, v2 = Bq.y, e3 = Bq.z, v3 = Bq.w;           \
            const float e4 = Cq.x, v4 = Cq.y, e5 = Cq.z, v5 = Cq.w;           \
            const float t12 = e1 + e2, t34 = e3 + e4;                         \
            const float rs0 = e0 + t12, rs1 = t12 + e3;                       \
            const float rs2 = e2 + t34, rs3 = t34 + e5;                       \
            (s)[0] += rs0; (s)[1] += rs1; (s)[2] += rs2; (s)[3] += rs3;       \
            (s)[4] += e2 - e0; (s)[5] += e3 - e1;                             \
            (s)[6] += e4 - e2; (s)[7] += e5 - e3;                             \
            if (r == 0) { (s)[8] -= rs0; (s)[9] -= rs1;                       \
                          (s)[10] -= rs2; (s)[11] -= rs3; }                   \
            if (r == 2) { (s)[8] += rs0; (s)[9] += rs1;                       \
                          (s)[10] += rs2; (s)[11] += rs3; }                   \
            const float u12 = v1 + v2, u34 = v3 + v4;                         \
            (s)[12] += v0 + u12; (s)[13] += u12 + v3;                         \
            (s)[14] += v2 + u34; (s)[15] += u34 + v5;                         \
        }

    float p[16], c[16], n[16];
    #pragma unroll
    for (int k = 0; k < 16; k++) { p[k] = 0.f; c[k] = 0.f; }

    // prologue: slice 0 -> buf0
    PUBLISH(0);
    #pragma unroll
    for (int j = 0; j < 5; j++) rv[j] = pred[j] ? __ldg(xc + HW + off[j]) : 0.f;
    __syncthreads();
    ACCUM(c, 0);

    const float hf = (float)(h0 + ty);
    const float wf = (float)(w0 + 4 * tx);
    const size_t pixbase = (size_t)(h0 + ty) * WW + (w0 + 4 * tx);
    float* pcoord = out + (size_t)bc * 3 * CHV + pixbase;
    float* pval   = out + (size_t)BC * 3 * CHV + (size_t)bc * CHV + pixbase;

    #pragma unroll 4
    for (int d = 0; d < DD; d++) {
        #pragma unroll
        for (int k = 0; k < 16; k++) n[k] = 0.f;

        if (d + 1 < DD) {
            const int buf = (d + 1) & 1;
            PUBLISH(buf);                       // slice d+1
            if (d + 2 < DD) {                   // prefetch slice d+2
                const float* xs2 = xc + (size_t)(d + 2) * HW;
                #pragma unroll
                for (int j = 0; j < 5; j++)
                    rv[j] = pred[j] ? __ldg(xs2 + off[j]) : 0.f;
            }
            __syncthreads();                    // one barrier per slice
            ACCUM(n, buf);
        }

        float inv[4];
        #pragma unroll
        for (int k = 0; k < 4; k++)
            inv[k] = __fdividef(1.0f, p[k] + c[k] + n[k] + 1e-8f);

        const float df = (float)d;
        float4 z4 = make_float4(df + (n[0] - p[0]) * inv[0],
                                df + (n[1] - p[1]) * inv[1],
                                df + (n[2] - p[2]) * inv[2],
                                df + (n[3] - p[3]) * inv[3]);
        float4 x4 = make_float4(wf        + (p[4] + c[4] + n[4]) * inv[0],
                                wf + 1.f  + (p[5] + c[5] + n[5]) * inv[1],
                                wf + 2.f  + (p[6] + c[6] + n[6]) * inv[2],
                                wf + 3.f  + (p[7] + c[7] + n[7]) * inv[3]);
        float4 y4 = make_float4(hf + (p[8]  + c[8]  + n[8])  * inv[0],
                                hf + (p[9]  + c[9]  + n[9])  * inv[1],
                                hf + (p[10] + c[10] + n[10]) * inv[2],
                                hf + (p[11] + c[11] + n[11]) * inv[3]);
        float4 v4 = make_float4((p[12] + c[12] + n[12]) * inv[0],
                                (p[13] + c[13] + n[13]) * inv[1],
                                (p[14] + c[14] + n[14]) * inv[2],
                                (p[15] + c[15] + n[15]) * inv[3]);

        __stcs(reinterpret_cast<float4*>(pcoord),           z4);
        __stcs(reinterpret_cast<float4*>(pcoord + CHV),     x4);
        __stcs(reinterpret_cast<float4*>(pcoord + 2 * CHV), y4);
        __stcs(reinterpret_cast<float4*>(pval),             v4);

        pcoord += HW;
        pval   += HW;

        #pragma unroll
        for (int k = 0; k < 16; k++) { p[k] = c[k]; c[k] = n[k]; }
    }
}

extern "C" void kernel_launch(void* const* d_in, const int* in_sizes, int n_in,
                              void* d_out, int out_size) {
    const float* x = (const float*)d_in[0];
    float* out = (float*)d_out;
    softargmax_kernel<<<dim3(WW / TWPIX, HH / TH, BC), NT>>>(x, out);
}

// round 7
// speedup vs baseline: 1.4005x; 1.4005x over previous
#include <cuda_runtime.h>

// (B,C,D,H,W) = (4,8,16,256,256), k=3, stride=1, pad=1
#define BC   32
#define DD   16
#define HH   256
#define WW   256
#define HW   (HH*WW)
#define CHV  (DD*HW)

#define TH    16              // tile height (= #warps)
#define TWPIX 64              // tile width in pixels (2 px / lane)
#define ROWS  (TH+2)          // 18
#define COLS  68              // col0 pad, col1 = w0-1 halo, cols2..65 data, col66 = w0+64 halo, col67 pad
#define TS    (ROWS*COLS)     // 1224
#define NT    (TH*32)         // 512

__global__ void __launch_bounds__(NT, 2)
softargmax_kernel(const float* __restrict__ x, float* __restrict__ out)
{
    const int bc = blockIdx.z;
    const int h0 = blockIdx.y * TH;
    const int w0 = blockIdx.x * TWPIX;
    const int tid = threadIdx.x;
    const int tx = tid & 31;
    const int ty = tid >> 5;

    // double-buffered (e, e*x) slice tiles
    __shared__ __align__(16) float2 tile[2][TS];

    const float* __restrict__ xc = x + (size_t)bc * CHV;

    // 3 fill slots cover TS=1224 (slot2 partial: tid<200)
    int  off[3];
    bool inr[3], pred[3];
    #pragma unroll
    for (int j = 0; j < 3; j++) {
        int i = tid + j * NT;
        int r = i / COLS, c = i % COLS;
        int hh = h0 + r - 1;          // rows: h0-1 .. h0+16
        int ww = w0 + c - 2;          // cols: data/halo at c in [1,66]
        inr[j]  = (i < TS);
        pred[j] = inr[j] && (c >= 1) && (c <= 66) &&
                  (hh >= 0) && (hh < HH) && (ww >= 0) && (ww < WW);
        off[j]  = pred[j] ? hh * WW + ww : 0;
    }

    float rv[3];
    #pragma unroll
    for (int j = 0; j < 3; j++) rv[j] = pred[j] ? __ldg(xc + off[j]) : 0.f;

    #define PUBLISH(BUF)                                                      \
        _Pragma("unroll")                                                     \
        for (int j = 0; j < 3; j++) {                                         \
            if (inr[j]) {                                                     \
                float e = pred[j] ? __expf(rv[j]) : 0.f;                      \
                tile[BUF][tid + j * NT] = make_float2(e, e * rv[j]);          \
            }                                                                 \
        }

    // s[0..3]={sum,xnum,ynum,vnum} px0 ; s[4..7] px1
    // own pixels (w0+2tx, w0+2tx+1) live at float2 cols (2+2tx, 3+2tx): 16B-aligned float4
    #define ACCUM(s, BUF)                                                     \
        _Pragma("unroll")                                                     \
        for (int r = 0; r < 3; r++) {                                         \
            const float4 A = *reinterpret_cast<const float4*>(                \
                &tile[BUF][(ty + r) * COLS + 2 + 2 * tx]);                    \
            float eL = __shfl_up_sync(0xFFFFFFFFu, A.z, 1);                   \
            float vL = __shfl_up_sync(0xFFFFFFFFu, A.w, 1);                   \
            float eR = __shfl_down_sync(0xFFFFFFFFu, A.x, 1);                 \
            float vR = __shfl_down_sync(0xFFFFFFFFu, A.y, 1);                 \
            if (tx == 0) {                                                    \
                float2 hl = tile[BUF][(ty + r) * COLS + 1];                   \
                eL = hl.x; vL = hl.y;                                         \
            }                                                                 \
            if (tx == 31) {                                                   \
                float2 hr = tile[BUF][(ty + r) * COLS + 66];                  \
                eR = hr.x; vR = hr.y;                                         \
            }                                                                 \
            const float t = A.x + A.z;                                        \
            const float rs0 = eL + t, rs1 = t + eR;                           \
            (s)[0] += rs0;          (s)[4] += rs1;                            \
            (s)[1] += A.z - eL;     (s)[5] += eR - A.x;                       \
            if (r == 0) { (s)[2] -= rs0; (s)[6] -= rs1; }                     \
            if (r == 2) { (s)[2] += rs0; (s)[6] += rs1; }                     \
            const float u = A.y + A.w;                                        \
            (s)[3] += vL + u;       (s)[7] += u + vR;                         \
        }

    float p[8], c[8], n[8];
    #pragma unroll
    for (int k = 0; k < 8; k++) { p[k] = 0.f; c[k] = 0.f; }

    // prologue: slice 0 -> buf0
    PUBLISH(0);
    #pragma unroll
    for (int j = 0; j < 3; j++) rv[j] = pred[j] ? __ldg(xc + HW + off[j]) : 0.f;
    __syncthreads();
    ACCUM(c, 0);

    const float hf = (float)(h0 + ty);
    const float wf = (float)(w0 + 2 * tx);
    const size_t pixbase = (size_t)(h0 + ty) * WW + (w0 + 2 * tx);
    float* pcoord = out + (size_t)bc * 3 * CHV + pixbase;
    float* pval   = out + (size_t)BC * 3 * CHV + (size_t)bc * CHV + pixbase;

    #pragma unroll
    for (int d = 0; d < DD; d++) {
        #pragma unroll
        for (int k = 0; k < 8; k++) n[k] = 0.f;

        if (d + 1 < DD) {
            const int buf = (d + 1) & 1;
            PUBLISH(buf);                       // slice d+1
            if (d + 2 < DD) {                   // prefetch slice d+2
                const float* xs2 = xc + (size_t)(d + 2) * HW;
                #pragma unroll
                for (int j = 0; j < 3; j++)
                    rv[j] = pred[j] ? __ldg(xs2 + off[j]) : 0.f;
            }
            __syncthreads();                    // one barrier per slice
            ACCUM(n, buf);
        }

        const float inv0 = __fdividef(1.0f, p[0] + c[0] + n[0] + 1e-8f);
        const float inv1 = __fdividef(1.0f, p[4] + c[4] + n[4] + 1e-8f);
        const float df = (float)d;

        float2 z2 = make_float2(df + (n[0] - p[0]) * inv0,
                                df + (n[4] - p[4]) * inv1);
        float2 x2 = make_float2(wf       + (p[1] + c[1] + n[1]) * inv0,
                                wf + 1.f + (p[5] + c[5] + n[5]) * inv1);
        float2 y2 = make_float2(hf + (p[2] + c[2] + n[2]) * inv0,
                                hf + (p[6] + c[6] + n[6]) * inv1);
        float2 v2 = make_float2((p[3] + c[3] + n[3]) * inv0,
                                (p[7] + c[7] + n[7]) * inv1);

        __stcs(reinterpret_cast<float2*>(pcoord),           z2);
        __stcs(reinterpret_cast<float2*>(pcoord + CHV),     x2);
        __stcs(reinterpret_cast<float2*>(pcoord + 2 * CHV), y2);
        __stcs(reinterpret_cast<float2*>(pval),             v2);

        pcoord += HW;
        pval   += HW;

        #pragma unroll
        for (int k = 0; k < 8; k++) { p[k] = c[k]; c[k] = n[k]; }
    }
}

extern "C" void kernel_launch(void* const* d_in, const int* in_sizes, int n_in,
                              void* d_out, int out_size) {
    const float* x = (const float*)d_in[0];
    float* out = (float*)d_out;
    softargmax_kernel<<<dim3(WW / TWPIX, HH / TH, BC), NT>>>(x, out);
}

// round 8
// speedup vs baseline: 1.5014x; 1.0721x over previous
#include <cuda_runtime.h>
#include <cuda_fp16.h>

// (B,C,D,H,W) = (4,8,16,256,256), k=3, stride=1, pad=1
#define BC   32
#define DD   16
#define HH   256
#define WW   256
#define HW   (HH*WW)
#define CHV  (DD*HW)

#define TH    16              // tile height (= #warps)
#define TWPIX 64              // tile width in pixels (2 px / lane)
#define ROWS  (TH+2)          // 18
#define COLS  68              // col1 = w0-1 halo, cols2..65 data, col66 = w0+64 halo
#define TS    (ROWS*COLS)     // 1224
#define NT    (TH*32)         // 512

__device__ __forceinline__ __half2 u2h(unsigned int u) {
    return *reinterpret_cast<__half2*>(&u);
}
__device__ __forceinline__ unsigned int h2u(__half2 h) {
    return *reinterpret_cast<unsigned int*>(&h);
}

__global__ void __launch_bounds__(NT, 2)
softargmax_kernel(const float* __restrict__ x, float* __restrict__ out)
{
    const int bc = blockIdx.z;
    const int h0 = blockIdx.y * TH;
    const int w0 = blockIdx.x * TWPIX;
    const int tid = threadIdx.x;
    const int tx = tid & 31;
    const int ty = tid >> 5;

    // double-buffered half2(e, e*x) slice tiles
    __shared__ __align__(16) __half2 tile[2][TS];

    const float* __restrict__ xc = x + (size_t)bc * CHV;

    // 3 fill slots cover TS=1224 (slot2 partial)
    int  off[3];
    bool inr[3], pred[3];
    #pragma unroll
    for (int j = 0; j < 3; j++) {
        int i = tid + j * NT;
        int r = i / COLS, c = i % COLS;
        int hh = h0 + r - 1;
        int ww = w0 + c - 2;
        inr[j]  = (i < TS);
        pred[j] = inr[j] && (c >= 1) && (c <= 66) &&
                  (hh >= 0) && (hh < HH) && (ww >= 0) && (ww < WW);
        off[j]  = pred[j] ? hh * WW + ww : 0;
    }

    float rv[3];
    #pragma unroll
    for (int j = 0; j < 3; j++) rv[j] = pred[j] ? __ldg(xc + off[j]) : 0.f;

    #define PUBLISH(BUF)                                                      \
        _Pragma("unroll")                                                     \
        for (int j = 0; j < 3; j++) {                                         \
            if (inr[j]) {                                                     \
                float e = pred[j] ? __expf(rv[j]) : 0.f;                      \
                tile[BUF][tid + j * NT] = __floats2half2_rn(e, e * rv[j]);    \
            }                                                                 \
        }

    // s[0]=(Σe,Σv) px0  s[1]=xnum px0  s[2]=ynum px0 ; s[3..5] px1
    #define ACCUM(s, BUF)                                                     \
        _Pragma("unroll")                                                     \
        for (int r = 0; r < 3; r++) {                                         \
            const uint2 u = *reinterpret_cast<const uint2*>(                  \
                &tile[BUF][(ty + r) * COLS + 2 + 2 * tx]);                    \
            unsigned int uL = __shfl_up_sync(0xFFFFFFFFu, u.y, 1);            \
            unsigned int uR = __shfl_down_sync(0xFFFFFFFFu, u.x, 1);          \
            if (tx == 0)                                                      \
                uL = *reinterpret_cast<const unsigned int*>(                  \
                    &tile[BUF][(ty + r) * COLS + 1]);                         \
            if (tx == 31)                                                     \
                uR = *reinterpret_cast<const unsigned int*>(                  \
                    &tile[BUF][(ty + r) * COLS + 66]);                        \
            const __half2 hc0 = u2h(u.x), hc1 = u2h(u.y);                     \
            const __half2 hL = u2h(uL), hR = u2h(uR);                         \
            const __half2 t = __hadd2(hc0, hc1);                              \
            const __half2 rs0 = __hadd2(hL, t);                               \
            const __half2 rs1 = __hadd2(t, hR);                               \
            (s)[0] = __hadd2((s)[0], rs0);                                    \
            (s)[3] = __hadd2((s)[3], rs1);                                    \
            (s)[1] = __hadd2((s)[1], __hsub2(hc1, hL));                       \
            (s)[4] = __hadd2((s)[4], __hsub2(hR, hc0));                       \
            if (r == 0) { (s)[2] = __hsub2((s)[2], rs0);                      \
                          (s)[5] = __hsub2((s)[5], rs1); }                    \
            if (r == 2) { (s)[2] = __hadd2((s)[2], rs0);                      \
                          (s)[5] = __hadd2((s)[5], rs1); }                    \
        }

    const __half2 zero = __floats2half2_rn(0.f, 0.f);
    __half2 p[6], c[6], n[6];
    #pragma unroll
    for (int k = 0; k < 6; k++) { p[k] = zero; c[k] = zero; }

    // prologue: slice 0 -> buf0
    PUBLISH(0);
    #pragma unroll
    for (int j = 0; j < 3; j++) rv[j] = pred[j] ? __ldg(xc + HW + off[j]) : 0.f;
    __syncthreads();
    ACCUM(c, 0);

    const float hf = (float)(h0 + ty);
    const float wf = (float)(w0 + 2 * tx);
    const size_t pixbase = (size_t)(h0 + ty) * WW + (w0 + 2 * tx);
    float* pcoord = out + (size_t)bc * 3 * CHV + pixbase;
    float* pval   = out + (size_t)BC * 3 * CHV + (size_t)bc * CHV + pixbase;

    #pragma unroll
    for (int d = 0; d < DD; d++) {
        #pragma unroll
        for (int k = 0; k < 6; k++) n[k] = zero;

        if (d + 1 < DD) {
            const int buf = (d + 1) & 1;
            PUBLISH(buf);                       // slice d+1
            if (d + 2 < DD) {                   // prefetch slice d+2
                const float* xs2 = xc + (size_t)(d + 2) * HW;
                #pragma unroll
                for (int j = 0; j < 3; j++)
                    rv[j] = pred[j] ? __ldg(xs2 + off[j]) : 0.f;
            }
            __syncthreads();                    // one barrier per slice
            ACCUM(n, buf);
        }

        // totals
        const __half2 tot0 = __hadd2(__hadd2(p[0], c[0]), n[0]);
        const __half2 tot1 = __hadd2(__hadd2(p[3], c[3]), n[3]);
        const __half2 zn0h = __hsub2(n[0], p[0]);
        const __half2 zn1h = __hsub2(n[3], p[3]);
        const __half2 xn0h = __hadd2(__hadd2(p[1], c[1]), n[1]);
        const __half2 xn1h = __hadd2(__hadd2(p[4], c[4]), n[4]);
        const __half2 yn0h = __hadd2(__hadd2(p[2], c[2]), n[2]);
        const __half2 yn1h = __hadd2(__hadd2(p[5], c[5]), n[5]);

        const float inv0 = __fdividef(1.0f, __low2float(tot0) + 1e-8f);
        const float inv1 = __fdividef(1.0f, __low2float(tot1) + 1e-8f);
        const float df = (float)d;

        float2 z2 = make_float2(df + __low2float(zn0h) * inv0,
                                df + __low2float(zn1h) * inv1);
        float2 x2 = make_float2(wf       + __low2float(xn0h) * inv0,
                                wf + 1.f + __low2float(xn1h) * inv1);
        float2 y2 = make_float2(hf + __low2float(yn0h) * inv0,
                                hf + __low2float(yn1h) * inv1);
        float2 v2 = make_float2(__high2float(tot0) * inv0,
                                __high2float(tot1) * inv1);

        __stcs(reinterpret_cast<float2*>(pcoord),           z2);
        __stcs(reinterpret_cast<float2*>(pcoord + CHV),     x2);
        __stcs(reinterpret_cast<float2*>(pcoord + 2 * CHV), y2);
        __stcs(reinterpret_cast<float2*>(pval),             v2);

        pcoord += HW;
        pval   += HW;

        #pragma unroll
        for (int k = 0; k < 6; k++) { p[k] = c[k]; c[k] = n[k]; }
    }
}

extern "C" void kernel_launch(void* const* d_in, const int* in_sizes, int n_in,
                              void* d_out, int out_size) {
    const float* x = (const float*)d_in[0];
    float* out = (float*)d_out;
    softargmax_kernel<<<dim3(WW / TWPIX, HH / TH, BC), NT>>>(x, out);
}